// round 16
// baseline (speedup 1.0000x reference)
#include <cuda_runtime.h>
#include <cuda_fp16.h>
#include <cstdint>

#define BATCH 16
#define LQ 1024
#define LK 2048
#define DIM 4096

// ---------------- scratch (static device allocations) ----------------
__device__ __half g_Qh[(size_t)BATCH * LQ * DIM];   // 128 MiB f16(Q)
__device__ __half g_Ql[(size_t)BATCH * LQ * DIM];   // 128 MiB f16(Q - f16Q)
__device__ __half g_Kh[(size_t)BATCH * LK * DIM];   // 256 MiB f16(K)
__device__ __half g_Kl[(size_t)BATCH * LK * DIM];   // 256 MiB f16 residual
__device__ __half g_Kth[(size_t)BATCH * DIM * LK];  // 256 MiB K^T f16
__device__ float g_S[(size_t)BATCH * LQ * LK];      // 128 MiB
__device__ __half g_Ph[(size_t)BATCH * LQ * LK];    // 64 MiB

// ---------------- helpers ----------------
__device__ __forceinline__ uint32_t smem_u32(const void* p) {
  uint32_t a;
  asm("{ .reg .u64 t; cvta.to.shared.u64 t, %1; cvt.u32.u64 %0, t; }"
      : "=r"(a) : "l"(p));
  return a;
}
__device__ __forceinline__ void cp16(uint32_t s, const void* g) {
  asm volatile("cp.async.cg.shared.global [%0], [%1], 16;" :: "r"(s), "l"(g));
}
#define CP_COMMIT() asm volatile("cp.async.commit_group;" ::: "memory")
#define CP_WAIT1()  asm volatile("cp.async.wait_group 1;" ::: "memory")

#define LDSM4(R0, R1, R2, R3, A)                                              \
  asm volatile("ldmatrix.sync.aligned.m8n8.x4.shared.b16 {%0,%1,%2,%3}, [%4];"\
               : "=r"(R0), "=r"(R1), "=r"(R2), "=r"(R3) : "r"(A))

__device__ __forceinline__ void mma_f32acc(float* c, const uint32_t* a,
                                           const uint32_t* b) {
  asm volatile(
      "mma.sync.aligned.m16n8k16.row.col.f32.f16.f16.f32 "
      "{%0,%1,%2,%3}, {%4,%5,%6,%7}, {%8,%9}, {%0,%1,%2,%3};"
      : "+f"(c[0]), "+f"(c[1]), "+f"(c[2]), "+f"(c[3])
      : "r"(a[0]), "r"(a[1]), "r"(a[2]), "r"(a[3]), "r"(b[0]), "r"(b[1]));
}
__device__ __forceinline__ void mma_f16acc(uint32_t* c, const uint32_t* a,
                                           const uint32_t* b) {
  asm volatile(
      "mma.sync.aligned.m16n8k16.row.col.f16.f16.f16.f16 "
      "{%0,%1}, {%2,%3,%4,%5}, {%6,%7}, {%0,%1};"
      : "+r"(c[0]), "+r"(c[1])
      : "r"(a[0]), "r"(a[1]), "r"(a[2]), "r"(a[3]), "r"(b[0]), "r"(b[1]));
}

// ---------------- conversion kernels ----------------
__global__ __launch_bounds__(256) void convert_q(const float4* __restrict__ Q) {
  size_t i = (size_t)blockIdx.x * 256 + threadIdx.x;
  float4 v = Q[i];
  float f[4] = {v.x, v.y, v.z, v.w};
  __half h[4], l[4];
#pragma unroll
  for (int j = 0; j < 4; ++j) {
    h[j] = __float2half_rn(f[j]);
    l[j] = __float2half_rn(f[j] - __half2float(h[j]));
  }
  *(uint2*)(g_Qh + 4 * i) = *(uint2*)h;
  *(uint2*)(g_Ql + 4 * i) = *(uint2*)l;
}

// K -> Kh/Kl (row-major) and Kth (transposed [d][k]).
// 64x64 tiles, 2 elems/thread: all global writes are 128B/warp half2.
__global__ __launch_bounds__(256) void convert_kt(const float* __restrict__ K) {
  __shared__ float tile[64][65];  // [d_local][k_local]
  const int b = blockIdx.z, k0 = blockIdx.y * 64, d0 = blockIdx.x * 64;
  const float* Kb = K + (size_t)b * LK * DIM;
  __half* Khb = g_Kh + (size_t)b * LK * DIM;
  __half* Klb = g_Kl + (size_t)b * LK * DIM;
  __half* Kthb = g_Kth + (size_t)b * DIM * LK;
  const int tx = threadIdx.x, ty = threadIdx.y;
#pragma unroll
  for (int r = 0; r < 8; ++r) {
    int kl = ty + 8 * r;
    int k = k0 + kl;
    float2 v = *(const float2*)(Kb + (size_t)k * DIM + d0 + 2 * tx);
    __half hx = __float2half_rn(v.x), hy = __float2half_rn(v.y);
    __half lx = __float2half_rn(v.x - __half2float(hx));
    __half ly = __float2half_rn(v.y - __half2float(hy));
    *(__half2*)(Khb + (size_t)k * DIM + d0 + 2 * tx) = __halves2half2(hx, hy);
    *(__half2*)(Klb + (size_t)k * DIM + d0 + 2 * tx) = __halves2half2(lx, ly);
    tile[2 * tx][kl] = v.x;
    tile[2 * tx + 1][kl] = v.y;
  }
  __syncthreads();
#pragma unroll
  for (int r = 0; r < 8; ++r) {
    int dl = ty + 8 * r;
    int d = d0 + dl;
    float a = tile[dl][2 * tx], c = tile[dl][2 * tx + 1];
    *(__half2*)(Kthb + (size_t)d * LK + k0 + 2 * tx) =
        __halves2half2(__float2half_rn(a), __float2half_rn(c));
  }
}

// =====================================================================
// QK GEMM: S = (Qh+Ql)·(Kh+Kl)^T, 3 products (hh f32-acc; hl/lh f16-acc)
// CTA 128x128, BK=64, 512 threads (16 warps as 4Mx4N of 32x32),
// 3-stage cp.async (64KB/stage), ONE barrier per iteration.
// =====================================================================
#define QK_OFF_AH 0
#define QK_OFF_AL 16384
#define QK_OFF_BH 32768
#define QK_OFF_BL 49152
#define QK_STAGE 65536
#define QK_SMEM (3 * QK_STAGE)

__device__ __forceinline__ void qk_load_stage(uint32_t stg, const __half* Ah,
                                              const __half* Al,
                                              const __half* Bh,
                                              const __half* Bl, int koff,
                                              int tid) {
#pragma unroll
  for (int it = 0; it < 2; ++it) {
    int idx = tid + 512 * it;  // 1024 = 128 rows x 8 chunks(16B)
    int r = idx >> 3, c = idx & 7;
    uint32_t so = (uint32_t)(r * 128 + ((c ^ (r & 7)) << 4));
    size_t go = (size_t)r * DIM + koff + c * 8;
    cp16(stg + QK_OFF_AH + so, Ah + go);
    cp16(stg + QK_OFF_AL + so, Al + go);
    cp16(stg + QK_OFF_BH + so, Bh + go);
    cp16(stg + QK_OFF_BL + so, Bl + go);
  }
}

__global__ __launch_bounds__(512, 1) void qk_mma() {
  extern __shared__ char smem_raw[];
  const uint32_t smem = smem_u32(smem_raw);
  const int tid = threadIdx.x;
  const int lane = tid & 31, wid = tid >> 5;  // 16 warps
  const int wm = wid & 3, wn = wid >> 2;      // 4x4 grid of 32x32 warp tiles
  const int b = blockIdx.z;
  const int n0 = blockIdx.x * 128, m0 = blockIdx.y * 128;

  const __half* Ah = g_Qh + (size_t)b * LQ * DIM + (size_t)m0 * DIM;
  const __half* Al = g_Ql + (size_t)b * LQ * DIM + (size_t)m0 * DIM;
  const __half* Bh = g_Kh + (size_t)b * LK * DIM + (size_t)n0 * DIM;
  const __half* Bl = g_Kl + (size_t)b * LK * DIM + (size_t)n0 * DIM;

  const int g = lane >> 3, rr = lane & 7;
  const int grow = ((g & 1) << 3) + rr;  // row within 16-row block
  const int g2 = g >> 1;                 // k-half selector
  const int rowA = wm * 32 + grow;
  const int rowB = wn * 32 + grow;
  const uint32_t baseA = (uint32_t)(rowA * 128);
  const uint32_t baseB = (uint32_t)(rowB * 128);

  float acc[2][4][4] = {};
  uint32_t cacc[2][4][2] = {};

  constexpr int NITER = DIM / 64;  // 64
  qk_load_stage(smem + 0 * QK_STAGE, Ah, Al, Bh, Bl, 0, tid);
  CP_COMMIT();
  qk_load_stage(smem + 1 * QK_STAGE, Ah, Al, Bh, Bl, 64, tid);
  CP_COMMIT();

  int sidx = 0;  // stage of iteration i (mod 3)
#pragma unroll 1
  for (int i = 0; i < NITER; ++i) {
    CP_WAIT1();
    __syncthreads();  // orders: stage(i) data ready AND all warps done
                      // reading the ring slot the prefetch below overwrites
    if (i + 2 < NITER) {
      int ps = sidx + 2;
      if (ps >= 3) ps -= 3;
      qk_load_stage(smem + ps * QK_STAGE, Ah, Al, Bh, Bl, (i + 2) * 64, tid);
    }
    CP_COMMIT();

    const uint32_t stg = smem + sidx * QK_STAGE;
#pragma unroll
    for (int kk = 0; kk < 4; ++kk) {
      const uint32_t swzA = (uint32_t)((((kk << 1) | g2) ^ rr) << 4);
      uint32_t a_h[2][4], a_l[2][4], b_h[4][2], b_l[4][2];
#pragma unroll
      for (int mt = 0; mt < 2; ++mt) {
        LDSM4(a_h[mt][0], a_h[mt][1], a_h[mt][2], a_h[mt][3],
              stg + QK_OFF_AH + baseA + mt * 2048 + swzA);
        LDSM4(a_l[mt][0], a_l[mt][1], a_l[mt][2], a_l[mt][3],
              stg + QK_OFF_AL + baseA + mt * 2048 + swzA);
      }
#pragma unroll
      for (int p = 0; p < 2; ++p) {
        uint32_t r0, r1, r2, r3;
        LDSM4(r0, r1, r2, r3, stg + QK_OFF_BH + baseB + p * 2048 + swzA);
        b_h[2 * p][0] = r0; b_h[2 * p + 1][0] = r1;
        b_h[2 * p][1] = r2; b_h[2 * p + 1][1] = r3;
        LDSM4(r0, r1, r2, r3, stg + QK_OFF_BL + baseB + p * 2048 + swzA);
        b_l[2 * p][0] = r0; b_l[2 * p + 1][0] = r1;
        b_l[2 * p][1] = r2; b_l[2 * p + 1][1] = r3;
      }
#pragma unroll
      for (int mt = 0; mt < 2; ++mt)
#pragma unroll
        for (int nt = 0; nt < 4; ++nt)
          mma_f32acc(acc[mt][nt], a_h[mt], b_h[nt]);
#pragma unroll
      for (int mt = 0; mt < 2; ++mt)
#pragma unroll
        for (int nt = 0; nt < 4; ++nt)
          mma_f16acc(cacc[mt][nt], a_h[mt], b_l[nt]);
#pragma unroll
      for (int mt = 0; mt < 2; ++mt)
#pragma unroll
        for (int nt = 0; nt < 4; ++nt)
          mma_f16acc(cacc[mt][nt], a_l[mt], b_h[nt]);
    }
    if (++sidx == 3) sidx = 0;
  }

  const int erow = (lane >> 2), ecol = (lane & 3) * 2;
  float* Cb = g_S + (size_t)b * LQ * LK;
#pragma unroll
  for (int mt = 0; mt < 2; ++mt) {
#pragma unroll
    for (int nt = 0; nt < 4; ++nt) {
      int row = m0 + wm * 32 + mt * 16 + erow;
      int col = n0 + wn * 32 + nt * 8 + ecol;
      float2 c0 = __half22float2(*(__half2*)&cacc[mt][nt][0]);
      float2 c1 = __half22float2(*(__half2*)&cacc[mt][nt][1]);
      *(float2*)(Cb + (size_t)row * LK + col) =
          make_float2(acc[mt][nt][0] + c0.x, acc[mt][nt][1] + c0.y);
      *(float2*)(Cb + (size_t)(row + 8) * LK + col) =
          make_float2(acc[mt][nt][2] + c1.x, acc[mt][nt][3] + c1.y);
    }
  }
}

// =====================================================================
// PV GEMM: O = Ph·Kth^T, single f16 product (f32 acc).
// CTA 128x128, BK=64, 256 threads (8 warps as 2Mx4N of 64x32),
// 3-stage x 32KB = 96KB -> 2 CTAs/SM. ONE barrier per iteration.
// =====================================================================
#define PV_OFF_A 0
#define PV_OFF_B 16384
#define PV_STAGE 32768
#define PV_SMEM (3 * PV_STAGE)

__device__ __forceinline__ void pv_load_stage(uint32_t stg, const __half* A,
                                              const __half* B, int koff,
                                              int tid) {
#pragma unroll
  for (int it = 0; it < 4; ++it) {
    int idx = tid + 256 * it;  // 1024 = 128 rows x 8 chunks
    int r = idx >> 3, c = idx & 7;
    uint32_t so = (uint32_t)(r * 128 + ((c ^ (r & 7)) << 4));
    size_t go = (size_t)r * LK + koff + c * 8;
    cp16(stg + PV_OFF_A + so, A + go);
    cp16(stg + PV_OFF_B + so, B + go);
  }
}

__global__ __launch_bounds__(256, 2) void pv_mma(float* __restrict__ O) {
  extern __shared__ char smem_raw[];
  const uint32_t smem = smem_u32(smem_raw);
  const int tid = threadIdx.x;
  const int lane = tid & 31, wid = tid >> 5;
  const int wm = wid & 1, wn = wid >> 1;
  const int b = blockIdx.z;
  const int n0 = blockIdx.x * 128, m0 = blockIdx.y * 128;

  const __half* A = g_Ph + (size_t)b * LQ * LK + (size_t)m0 * LK;
  const __half* B = g_Kth + (size_t)b * DIM * LK + (size_t)n0 * LK;

  const int g = lane >> 3, rr = lane & 7;
  const int grow = ((g & 1) << 3) + rr;
  const int g2 = g >> 1;
  const int rowA = wm * 64 + grow;
  const int rowB = wn * 32 + grow;
  const uint32_t baseA = (uint32_t)(rowA * 128);
  const uint32_t baseB = (uint32_t)(rowB * 128);

  float acc[4][4][4] = {};

  constexpr int NITER = LK / 64;  // 32
  pv_load_stage(smem + 0 * PV_STAGE, A, B, 0, tid);
  CP_COMMIT();
  pv_load_stage(smem + 1 * PV_STAGE, A, B, 64, tid);
  CP_COMMIT();

  int sidx = 0;
#pragma unroll 1
  for (int i = 0; i < NITER; ++i) {
    CP_WAIT1();
    __syncthreads();  // orders: stage(i) data ready AND all warps done
                      // reading the ring slot the prefetch below overwrites
    if (i + 2 < NITER) {
      int ps = sidx + 2;
      if (ps >= 3) ps -= 3;
      pv_load_stage(smem + ps * PV_STAGE, A, B, (i + 2) * 64, tid);
    }
    CP_COMMIT();

    const uint32_t stg = smem + sidx * PV_STAGE;
#pragma unroll
    for (int kk = 0; kk < 4; ++kk) {
      const uint32_t swz = (uint32_t)((((kk << 1) | g2) ^ rr) << 4);
      uint32_t a[4][4], bb[4][2];
#pragma unroll
      for (int mt = 0; mt < 4; ++mt)
        LDSM4(a[mt][0], a[mt][1], a[mt][2], a[mt][3],
              stg + PV_OFF_A + baseA + mt * 2048 + swz);
#pragma unroll
      for (int p = 0; p < 2; ++p) {
        uint32_t r0, r1, r2, r3;
        LDSM4(r0, r1, r2, r3, stg + PV_OFF_B + baseB + p * 2048 + swz);
        bb[2 * p][0] = r0; bb[2 * p + 1][0] = r1;
        bb[2 * p][1] = r2; bb[2 * p + 1][1] = r3;
      }
#pragma unroll
      for (int mt = 0; mt < 4; ++mt)
#pragma unroll
        for (int nt = 0; nt < 4; ++nt)
          mma_f32acc(acc[mt][nt], a[mt], bb[nt]);
    }
    if (++sidx == 3) sidx = 0;
  }

  const int erow = (lane >> 2), ecol = (lane & 3) * 2;
  float* Cb = O + (size_t)b * LQ * DIM;
#pragma unroll
  for (int mt = 0; mt < 4; ++mt) {
#pragma unroll
    for (int nt = 0; nt < 4; ++nt) {
      int row = m0 + wm * 64 + mt * 16 + erow;
      int col = n0 + wn * 32 + nt * 8 + ecol;
      *(float2*)(Cb + (size_t)row * DIM + col) =
          make_float2(acc[mt][nt][0], acc[mt][nt][1]);
      *(float2*)(Cb + (size_t)(row + 8) * DIM + col) =
          make_float2(acc[mt][nt][2], acc[mt][nt][3]);
    }
  }
}

// ---------------- softmax: S (fp32) -> Ph (f16), vectorized ----------------
__global__ __launch_bounds__(256) void softmax_k() {
  const size_t ro = (size_t)blockIdx.x * LK;
  const float4* row4 = (const float4*)(g_S + ro);
  __half2* ph2 = (__half2*)(g_Ph + ro);
  const int t = threadIdx.x;

  float v[8];
  float m = -1e30f;
#pragma unroll
  for (int i = 0; i < 2; ++i) {
    float4 x = row4[t + 256 * i];
    v[4 * i + 0] = x.x; v[4 * i + 1] = x.y;
    v[4 * i + 2] = x.z; v[4 * i + 3] = x.w;
  }
#pragma unroll
  for (int i = 0; i < 8; ++i) m = fmaxf(m, v[i]);

  __shared__ float red[32];
#pragma unroll
  for (int o = 16; o; o >>= 1) m = fmaxf(m, __shfl_xor_sync(0xffffffffu, m, o));
  if ((t & 31) == 0) red[t >> 5] = m;
  __syncthreads();
  if (t < 32) {
    float x = (t < 8) ? red[t] : -1e30f;
#pragma unroll
    for (int o = 4; o; o >>= 1) x = fmaxf(x, __shfl_xor_sync(0xffffffffu, x, o));
    if (t == 0) red[0] = x;
  }
  __syncthreads();
  m = red[0];

  float s = 0.f;
#pragma unroll
  for (int i = 0; i < 8; ++i) {
    v[i] = __expf(v[i] - m);
    s += v[i];
  }
#pragma unroll
  for (int o = 16; o; o >>= 1) s += __shfl_xor_sync(0xffffffffu, s, o);
  __syncthreads();
  if ((t & 31) == 0) red[t >> 5] = s;
  __syncthreads();
  if (t < 32) {
    float x = (t < 8) ? red[t] : 0.f;
#pragma unroll
    for (int o = 4; o; o >>= 1) x += __shfl_xor_sync(0xffffffffu, x, o);
    if (t == 0) red[1] = x;
  }
  __syncthreads();
  const float inv = 1.f / red[1];
#pragma unroll
  for (int i = 0; i < 2; ++i) {
    ph2[2 * (t + 256 * i) + 0] =
        __floats2half2_rn(v[4 * i + 0] * inv, v[4 * i + 1] * inv);
    ph2[2 * (t + 256 * i) + 1] =
        __floats2half2_rn(v[4 * i + 2] * inv, v[4 * i + 3] * inv);
  }
}

// ---------------- launch ----------------
extern "C" void kernel_launch(void* const* d_in, const int* in_sizes, int n_in,
                              void* d_out, int out_size) {
  const float* Q = (const float*)d_in[0];
  const float* K = (const float*)d_in[1];
  float* O = (float*)d_out;

  cudaFuncSetAttribute(qk_mma, cudaFuncAttributeMaxDynamicSharedMemorySize,
                       QK_SMEM);
  cudaFuncSetAttribute(pv_mma, cudaFuncAttributeMaxDynamicSharedMemorySize,
                       PV_SMEM);

  convert_q<<<(int)(((size_t)BATCH * LQ * DIM / 4) / 256), 256>>>(
      (const float4*)Q);
  convert_kt<<<dim3(DIM / 64, LK / 64, BATCH), dim3(32, 8)>>>(K);
  qk_mma<<<dim3(LK / 128, LQ / 128, BATCH), 512, QK_SMEM>>>();
  softmax_k<<<BATCH * LQ, 256>>>();
  pv_mma<<<dim3(DIM / 128, LQ / 128, BATCH), 256, PV_SMEM>>>(O);
}

// round 17
// speedup vs baseline: 1.0021x; 1.0021x over previous
#include <cuda_runtime.h>
#include <cuda_fp16.h>
#include <cstdint>

#define BATCH 16
#define LQ 1024
#define LK 2048
#define DIM 4096

// ---------------- scratch (static device allocations) ----------------
__device__ __half g_Qh[(size_t)BATCH * LQ * DIM];   // 128 MiB f16(Q)
__device__ __half g_Ql[(size_t)BATCH * LQ * DIM];   // 128 MiB f16(Q - f16Q)
__device__ __half g_Kh[(size_t)BATCH * LK * DIM];   // 256 MiB f16(K)
__device__ __half g_Kl[(size_t)BATCH * LK * DIM];   // 256 MiB f16 residual
__device__ __half g_Kth[(size_t)BATCH * DIM * LK];  // 256 MiB K^T f16
__device__ float g_S[(size_t)BATCH * LQ * LK];      // 128 MiB
__device__ __half g_Ph[(size_t)BATCH * LQ * LK];    // 64 MiB

// ---------------- helpers ----------------
__device__ __forceinline__ uint32_t smem_u32(const void* p) {
  uint32_t a;
  asm("{ .reg .u64 t; cvta.to.shared.u64 t, %1; cvt.u32.u64 %0, t; }"
      : "=r"(a) : "l"(p));
  return a;
}
__device__ __forceinline__ void cp16(uint32_t s, const void* g) {
  asm volatile("cp.async.cg.shared.global [%0], [%1], 16;" :: "r"(s), "l"(g));
}
#define CP_COMMIT() asm volatile("cp.async.commit_group;" ::: "memory")
#define CP_WAIT1()  asm volatile("cp.async.wait_group 1;" ::: "memory")

#define LDSM4(R0, R1, R2, R3, A)                                              \
  asm volatile("ldmatrix.sync.aligned.m8n8.x4.shared.b16 {%0,%1,%2,%3}, [%4];"\
               : "=r"(R0), "=r"(R1), "=r"(R2), "=r"(R3) : "r"(A))

__device__ __forceinline__ void mma_f32acc(float* c, const uint32_t* a,
                                           const uint32_t* b) {
  asm volatile(
      "mma.sync.aligned.m16n8k16.row.col.f32.f16.f16.f32 "
      "{%0,%1,%2,%3}, {%4,%5,%6,%7}, {%8,%9}, {%0,%1,%2,%3};"
      : "+f"(c[0]), "+f"(c[1]), "+f"(c[2]), "+f"(c[3])
      : "r"(a[0]), "r"(a[1]), "r"(a[2]), "r"(a[3]), "r"(b[0]), "r"(b[1]));
}
__device__ __forceinline__ void mma_f16acc(uint32_t* c, const uint32_t* a,
                                           const uint32_t* b) {
  asm volatile(
      "mma.sync.aligned.m16n8k16.row.col.f16.f16.f16.f16 "
      "{%0,%1}, {%2,%3,%4,%5}, {%6,%7}, {%0,%1};"
      : "+r"(c[0]), "+r"(c[1])
      : "r"(a[0]), "r"(a[1]), "r"(a[2]), "r"(a[3]), "r"(b[0]), "r"(b[1]));
}

// ---------------- conversion kernels ----------------
__global__ __launch_bounds__(256) void convert_q(const float4* __restrict__ Q) {
  size_t i = (size_t)blockIdx.x * 256 + threadIdx.x;
  float4 v = Q[i];
  float f[4] = {v.x, v.y, v.z, v.w};
  __half h[4], l[4];
#pragma unroll
  for (int j = 0; j < 4; ++j) {
    h[j] = __float2half_rn(f[j]);
    l[j] = __float2half_rn(f[j] - __half2float(h[j]));
  }
  *(uint2*)(g_Qh + 4 * i) = *(uint2*)h;
  *(uint2*)(g_Ql + 4 * i) = *(uint2*)l;
}

// K -> Kh/Kl (row-major) and Kth (transposed [d][k], f16 only)  [R15-exact]
__global__ __launch_bounds__(256) void convert_kt(const float* __restrict__ K) {
  __shared__ float tile[32][33];
  const int b = blockIdx.z, k0 = blockIdx.y * 32, d0 = blockIdx.x * 32;
  const float* Kb = K + (size_t)b * LK * DIM;
  __half* Khb = g_Kh + (size_t)b * LK * DIM;
  __half* Klb = g_Kl + (size_t)b * LK * DIM;
  __half* Kthb = g_Kth + (size_t)b * DIM * LK;
  const int tx = threadIdx.x, ty = threadIdx.y;
#pragma unroll
  for (int i = 0; i < 4; ++i) {
    int k = k0 + ty + 8 * i;
    float v = Kb[(size_t)k * DIM + d0 + tx];
    __half h = __float2half_rn(v);
    Khb[(size_t)k * DIM + d0 + tx] = h;
    Klb[(size_t)k * DIM + d0 + tx] = __float2half_rn(v - __half2float(h));
    tile[ty + 8 * i][tx] = v;
  }
  __syncthreads();
#pragma unroll
  for (int i = 0; i < 4; ++i) {
    int d = d0 + ty + 8 * i;
    Kthb[(size_t)d * LK + k0 + tx] = __float2half_rn(tile[tx][ty + 8 * i]);
  }
}

// =====================================================================
// QK GEMM: S = (Qh+Ql)·(Kh+Kl)^T, 3 products (hh f32-acc; hl/lh f16-acc)
// CTA 128x128, BK=64, 512 threads (16 warps as 4Mx4N of 32x32),
// 3-stage cp.async (64KB/stage), ONE barrier per iteration.
// =====================================================================
#define QK_OFF_AH 0
#define QK_OFF_AL 16384
#define QK_OFF_BH 32768
#define QK_OFF_BL 49152
#define QK_STAGE 65536
#define QK_SMEM (3 * QK_STAGE)

__device__ __forceinline__ void qk_load_stage(uint32_t stg, const __half* Ah,
                                              const __half* Al,
                                              const __half* Bh,
                                              const __half* Bl, int koff,
                                              int tid) {
#pragma unroll
  for (int it = 0; it < 2; ++it) {
    int idx = tid + 512 * it;  // 1024 = 128 rows x 8 chunks(16B)
    int r = idx >> 3, c = idx & 7;
    uint32_t so = (uint32_t)(r * 128 + ((c ^ (r & 7)) << 4));
    size_t go = (size_t)r * DIM + koff + c * 8;
    cp16(stg + QK_OFF_AH + so, Ah + go);
    cp16(stg + QK_OFF_AL + so, Al + go);
    cp16(stg + QK_OFF_BH + so, Bh + go);
    cp16(stg + QK_OFF_BL + so, Bl + go);
  }
}

__global__ __launch_bounds__(512, 1) void qk_mma() {
  extern __shared__ char smem_raw[];
  const uint32_t smem = smem_u32(smem_raw);
  const int tid = threadIdx.x;
  const int lane = tid & 31, wid = tid >> 5;  // 16 warps
  const int wm = wid & 3, wn = wid >> 2;      // 4x4 grid of 32x32 warp tiles
  const int b = blockIdx.z;
  const int n0 = blockIdx.x * 128, m0 = blockIdx.y * 128;

  const __half* Ah = g_Qh + (size_t)b * LQ * DIM + (size_t)m0 * DIM;
  const __half* Al = g_Ql + (size_t)b * LQ * DIM + (size_t)m0 * DIM;
  const __half* Bh = g_Kh + (size_t)b * LK * DIM + (size_t)n0 * DIM;
  const __half* Bl = g_Kl + (size_t)b * LK * DIM + (size_t)n0 * DIM;

  const int g = lane >> 3, rr = lane & 7;
  const int grow = ((g & 1) << 3) + rr;  // row within 16-row block
  const int g2 = g >> 1;                 // k-half selector
  const int rowA = wm * 32 + grow;
  const int rowB = wn * 32 + grow;
  const uint32_t baseA = (uint32_t)(rowA * 128);
  const uint32_t baseB = (uint32_t)(rowB * 128);

  float acc[2][4][4] = {};
  uint32_t cacc[2][4][2] = {};

  constexpr int NITER = DIM / 64;  // 64
  qk_load_stage(smem + 0 * QK_STAGE, Ah, Al, Bh, Bl, 0, tid);
  CP_COMMIT();
  qk_load_stage(smem + 1 * QK_STAGE, Ah, Al, Bh, Bl, 64, tid);
  CP_COMMIT();

  int sidx = 0;  // stage of iteration i (mod 3)
#pragma unroll 1
  for (int i = 0; i < NITER; ++i) {
    CP_WAIT1();
    __syncthreads();  // orders: stage(i) data ready AND all warps done
                      // reading the ring slot the prefetch below overwrites
    if (i + 2 < NITER) {
      int ps = sidx + 2;
      if (ps >= 3) ps -= 3;
      qk_load_stage(smem + ps * QK_STAGE, Ah, Al, Bh, Bl, (i + 2) * 64, tid);
    }
    CP_COMMIT();

    const uint32_t stg = smem + sidx * QK_STAGE;
#pragma unroll
    for (int kk = 0; kk < 4; ++kk) {
      const uint32_t swzA = (uint32_t)((((kk << 1) | g2) ^ rr) << 4);
      uint32_t a_h[2][4], a_l[2][4], b_h[4][2], b_l[4][2];
#pragma unroll
      for (int mt = 0; mt < 2; ++mt) {
        LDSM4(a_h[mt][0], a_h[mt][1], a_h[mt][2], a_h[mt][3],
              stg + QK_OFF_AH + baseA + mt * 2048 + swzA);
        LDSM4(a_l[mt][0], a_l[mt][1], a_l[mt][2], a_l[mt][3],
              stg + QK_OFF_AL + baseA + mt * 2048 + swzA);
      }
#pragma unroll
      for (int p = 0; p < 2; ++p) {
        uint32_t r0, r1, r2, r3;
        LDSM4(r0, r1, r2, r3, stg + QK_OFF_BH + baseB + p * 2048 + swzA);
        b_h[2 * p][0] = r0; b_h[2 * p + 1][0] = r1;
        b_h[2 * p][1] = r2; b_h[2 * p + 1][1] = r3;
        LDSM4(r0, r1, r2, r3, stg + QK_OFF_BL + baseB + p * 2048 + swzA);
        b_l[2 * p][0] = r0; b_l[2 * p + 1][0] = r1;
        b_l[2 * p][1] = r2; b_l[2 * p + 1][1] = r3;
      }
#pragma unroll
      for (int mt = 0; mt < 2; ++mt)
#pragma unroll
        for (int nt = 0; nt < 4; ++nt)
          mma_f32acc(acc[mt][nt], a_h[mt], b_h[nt]);
#pragma unroll
      for (int mt = 0; mt < 2; ++mt)
#pragma unroll
        for (int nt = 0; nt < 4; ++nt)
          mma_f16acc(cacc[mt][nt], a_h[mt], b_l[nt]);
#pragma unroll
      for (int mt = 0; mt < 2; ++mt)
#pragma unroll
        for (int nt = 0; nt < 4; ++nt)
          mma_f16acc(cacc[mt][nt], a_l[mt], b_h[nt]);
    }
    if (++sidx == 3) sidx = 0;
  }

  const int erow = (lane >> 2), ecol = (lane & 3) * 2;
  float* Cb = g_S + (size_t)b * LQ * LK;
#pragma unroll
  for (int mt = 0; mt < 2; ++mt) {
#pragma unroll
    for (int nt = 0; nt < 4; ++nt) {
      int row = m0 + wm * 32 + mt * 16 + erow;
      int col = n0 + wn * 32 + nt * 8 + ecol;
      float2 c0 = __half22float2(*(__half2*)&cacc[mt][nt][0]);
      float2 c1 = __half22float2(*(__half2*)&cacc[mt][nt][1]);
      *(float2*)(Cb + (size_t)row * LK + col) =
          make_float2(acc[mt][nt][0] + c0.x, acc[mt][nt][1] + c0.y);
      *(float2*)(Cb + (size_t)(row + 8) * LK + col) =
          make_float2(acc[mt][nt][2] + c1.x, acc[mt][nt][3] + c1.y);
    }
  }
}

// =====================================================================
// PV GEMM: O = Ph·Kth^T, single f16 product (f32 acc).
// CTA 128x128, BK=64, 256 threads (8 warps as 2Mx4N of 64x32),
// 3-stage x 32KB = 96KB -> 2 CTAs/SM. ONE barrier per iteration.
// =====================================================================
#define PV_OFF_A 0
#define PV_OFF_B 16384
#define PV_STAGE 32768
#define PV_SMEM (3 * PV_STAGE)

__device__ __forceinline__ void pv_load_stage(uint32_t stg, const __half* A,
                                              const __half* B, int koff,
                                              int tid) {
#pragma unroll
  for (int it = 0; it < 4; ++it) {
    int idx = tid + 256 * it;  // 1024 = 128 rows x 8 chunks
    int r = idx >> 3, c = idx & 7;
    uint32_t so = (uint32_t)(r * 128 + ((c ^ (r & 7)) << 4));
    size_t go = (size_t)r * LK + koff + c * 8;
    cp16(stg + PV_OFF_A + so, A + go);
    cp16(stg + PV_OFF_B + so, B + go);
  }
}

__global__ __launch_bounds__(256, 2) void pv_mma(float* __restrict__ O) {
  extern __shared__ char smem_raw[];
  const uint32_t smem = smem_u32(smem_raw);
  const int tid = threadIdx.x;
  const int lane = tid & 31, wid = tid >> 5;
  const int wm = wid & 1, wn = wid >> 1;
  const int b = blockIdx.z;
  const int n0 = blockIdx.x * 128, m0 = blockIdx.y * 128;

  const __half* A = g_Ph + (size_t)b * LQ * LK + (size_t)m0 * LK;
  const __half* B = g_Kth + (size_t)b * DIM * LK + (size_t)n0 * LK;

  const int g = lane >> 3, rr = lane & 7;
  const int grow = ((g & 1) << 3) + rr;
  const int g2 = g >> 1;
  const int rowA = wm * 64 + grow;
  const int rowB = wn * 32 + grow;
  const uint32_t baseA = (uint32_t)(rowA * 128);
  const uint32_t baseB = (uint32_t)(rowB * 128);

  float acc[4][4][4] = {};

  constexpr int NITER = LK / 64;  // 32
  pv_load_stage(smem + 0 * PV_STAGE, A, B, 0, tid);
  CP_COMMIT();
  pv_load_stage(smem + 1 * PV_STAGE, A, B, 64, tid);
  CP_COMMIT();

  int sidx = 0;
#pragma unroll 1
  for (int i = 0; i < NITER; ++i) {
    CP_WAIT1();
    __syncthreads();  // orders: stage(i) data ready AND all warps done
                      // reading the ring slot the prefetch below overwrites
    if (i + 2 < NITER) {
      int ps = sidx + 2;
      if (ps >= 3) ps -= 3;
      pv_load_stage(smem + ps * PV_STAGE, A, B, (i + 2) * 64, tid);
    }
    CP_COMMIT();

    const uint32_t stg = smem + sidx * PV_STAGE;
#pragma unroll
    for (int kk = 0; kk < 4; ++kk) {
      const uint32_t swz = (uint32_t)((((kk << 1) | g2) ^ rr) << 4);
      uint32_t a[4][4], bb[4][2];
#pragma unroll
      for (int mt = 0; mt < 4; ++mt)
        LDSM4(a[mt][0], a[mt][1], a[mt][2], a[mt][3],
              stg + PV_OFF_A + baseA + mt * 2048 + swz);
#pragma unroll
      for (int p = 0; p < 2; ++p) {
        uint32_t r0, r1, r2, r3;
        LDSM4(r0, r1, r2, r3, stg + PV_OFF_B + baseB + p * 2048 + swz);
        bb[2 * p][0] = r0; bb[2 * p + 1][0] = r1;
        bb[2 * p][1] = r2; bb[2 * p + 1][1] = r3;
      }
#pragma unroll
      for (int mt = 0; mt < 4; ++mt)
#pragma unroll
        for (int nt = 0; nt < 4; ++nt)
          mma_f32acc(acc[mt][nt], a[mt], bb[nt]);
    }
    if (++sidx == 3) sidx = 0;
  }

  const int erow = (lane >> 2), ecol = (lane & 3) * 2;
  float* Cb = O + (size_t)b * LQ * DIM;
#pragma unroll
  for (int mt = 0; mt < 4; ++mt) {
#pragma unroll
    for (int nt = 0; nt < 4; ++nt) {
      int row = m0 + wm * 64 + mt * 16 + erow;
      int col = n0 + wn * 32 + nt * 8 + ecol;
      *(float2*)(Cb + (size_t)row * DIM + col) =
          make_float2(acc[mt][nt][0], acc[mt][nt][1]);
      *(float2*)(Cb + (size_t)(row + 8) * DIM + col) =
          make_float2(acc[mt][nt][2], acc[mt][nt][3]);
    }
  }
}

// ---------------- softmax: S (fp32) -> Ph (f16), vectorized [R16] --------
__global__ __launch_bounds__(256) void softmax_k() {
  const size_t ro = (size_t)blockIdx.x * LK;
  const float4* row4 = (const float4*)(g_S + ro);
  __half2* ph2 = (__half2*)(g_Ph + ro);
  const int t = threadIdx.x;

  float v[8];
  float m = -1e30f;
#pragma unroll
  for (int i = 0; i < 2; ++i) {
    float4 x = row4[t + 256 * i];
    v[4 * i + 0] = x.x; v[4 * i + 1] = x.y;
    v[4 * i + 2] = x.z; v[4 * i + 3] = x.w;
  }
#pragma unroll
  for (int i = 0; i < 8; ++i) m = fmaxf(m, v[i]);

  __shared__ float red[32];
#pragma unroll
  for (int o = 16; o; o >>= 1) m = fmaxf(m, __shfl_xor_sync(0xffffffffu, m, o));
  if ((t & 31) == 0) red[t >> 5] = m;
  __syncthreads();
  if (t < 32) {
    float x = (t < 8) ? red[t] : -1e30f;
#pragma unroll
    for (int o = 4; o; o >>= 1) x = fmaxf(x, __shfl_xor_sync(0xffffffffu, x, o));
    if (t == 0) red[0] = x;
  }
  __syncthreads();
  m = red[0];

  float s = 0.f;
#pragma unroll
  for (int i = 0; i < 8; ++i) {
    v[i] = __expf(v[i] - m);
    s += v[i];
  }
#pragma unroll
  for (int o = 16; o; o >>= 1) s += __shfl_xor_sync(0xffffffffu, s, o);
  __syncthreads();
  if ((t & 31) == 0) red[t >> 5] = s;
  __syncthreads();
  if (t < 32) {
    float x = (t < 8) ? red[t] : 0.f;
#pragma unroll
    for (int o = 4; o; o >>= 1) x += __shfl_xor_sync(0xffffffffu, x, o);
    if (t == 0) red[1] = x;
  }
  __syncthreads();
  const float inv = 1.f / red[1];
#pragma unroll
  for (int i = 0; i < 2; ++i) {
    ph2[2 * (t + 256 * i) + 0] =
        __floats2half2_rn(v[4 * i + 0] * inv, v[4 * i + 1] * inv);
    ph2[2 * (t + 256 * i) + 1] =
        __floats2half2_rn(v[4 * i + 2] * inv, v[4 * i + 3] * inv);
  }
}

// ---------------- launch ----------------
extern "C" void kernel_launch(void* const* d_in, const int* in_sizes, int n_in,
                              void* d_out, int out_size) {
  const float* Q = (const float*)d_in[0];
  const float* K = (const float*)d_in[1];
  float* O = (float*)d_out;

  cudaFuncSetAttribute(qk_mma, cudaFuncAttributeMaxDynamicSharedMemorySize,
                       QK_SMEM);
  cudaFuncSetAttribute(pv_mma, cudaFuncAttributeMaxDynamicSharedMemorySize,
                       PV_SMEM);

  convert_q<<<(int)(((size_t)BATCH * LQ * DIM / 4) / 256), 256>>>(
      (const float4*)Q);
  convert_kt<<<dim3(DIM / 32, LK / 32, BATCH), dim3(32, 8)>>>(K);
  qk_mma<<<dim3(LK / 128, LQ / 128, BATCH), 512, QK_SMEM>>>();
  softmax_k<<<BATCH * LQ, 256>>>();
  pv_mma<<<dim3(DIM / 128, LQ / 128, BATCH), 256, PV_SMEM>>>(O);
}